// round 8
// baseline (speedup 1.0000x reference)
#include <cuda_runtime.h>
#include <math.h>

#define BB 8
#define C0 16
#define C1 64
#define C2 64
#define TT 12
#define NN 256
#define KTT 3
#define HH 8
#define T1 10
#define T2 8
#define ALPHA 0.2f

// ---------------- device scratch (no allocations allowed) ----------------
__device__ float g_v1[HH * C1];
__device__ float g_v2[HH * C1];
__device__ int   g_nbr[NN * NN];
__device__ int   g_cnt[NN];
__device__ float g_lnw[C2 * NN];            // transposed [c][n]
__device__ float g_lnb[C2 * NN];
__device__ float g_xg[BB * T1 * NN * C1];   // x_t1 in (b,t,n,c)
__device__ float g_e1[BB * T1 * NN * HH];   // [bt][n][h]  (float4-friendly)
__device__ float g_e2[BB * T1 * HH * NN];   // [bt][h][n]
__device__ float g_xs[BB * T1 * NN * C1];   // x_t1 + gat
__device__ float g_ys[BB * T2 * NN * C2];   // relu(conv2)+res, (bt,n,c)
__device__ float g_part[BB * T2 * 4 * 2];   // per-chunk LN partials {S,Q}

__device__ __forceinline__ float ftanh(float x) {
    x = fminf(fmaxf(x, -15.f), 15.f);
    float e = __expf(2.f * x);
    return (e - 1.f) / (e + 1.f);
}

// ---------------- K0: prep, parallelized over 16 blocks -------------------
__global__ void k0_prep(const float* __restrict__ adj,
                        const float* __restrict__ W,
                        const float* __restrict__ a,
                        const float* __restrict__ lnw,
                        const float* __restrict__ lnb) {
    int tid = threadIdx.x, lane = tid & 31, w = tid >> 5;
    int blk = blockIdx.x;

    if (blk == 0) {
        for (int idx = tid; idx < HH * C1; idx += 256) {
            int h = idx / C1, c = idx % C1;
            const float* Wr = W + (h * C1 + c) * C1;
            const float* ar = a + h * 2 * C1;
            float s1 = 0.f, s2 = 0.f;
            for (int d = 0; d < C1; d++) {
                float wv = Wr[d];
                s1 = fmaf(wv, ar[d], s1);
                s2 = fmaf(wv, ar[C1 + d], s2);
            }
            g_v1[idx] = s1;
            g_v2[idx] = s2;
        }
    }
    // CSR via warp ballot compaction: 16 rows per block, 2 per warp
    for (int r2 = 0; r2 < 2; r2++) {
        int i = blk * 16 + w * 2 + r2;
        const float* row = adj + i * NN;
        int cnt = 0;
#pragma unroll
        for (int c = 0; c < 8; c++) {
            int j = c * 32 + lane;
            bool bset = row[j] > 0.f;
            unsigned mask = __ballot_sync(0xffffffffu, bset);
            if (bset) {
                int pos = cnt + __popc(mask & ((1u << lane) - 1));
                g_nbr[i * NN + pos] = j;
            }
            cnt += __popc(mask);
        }
        if (lane == 0) g_cnt[i] = cnt;
        int cc = cnt > 96 ? 96 : cnt;
        int pc = ((cc + 31) >> 5) << 5;
        for (int k = cnt + lane; k < pc; k += 32) g_nbr[i * NN + k] = 0;
    }
    for (int idx = blk * 256 + tid; idx < NN * C2; idx += 16 * 256) {
        int n = idx / C2, c = idx % C2;
        g_lnw[c * NN + n] = lnw[idx];
        g_lnb[c * NN + n] = lnb[idx];
    }
}

// ---------------- K1: conv1 (register-tiled) + GLU + e-scores -------------
// grid (B*T1, 2): 128 nodes/block; 256 threads
// thread tile: 4 nodes x 4 co-pairs (filter+gate), 2 node passes
#define K1_SMEM ((48*128 + 48*128 + 128 + 128*67 + 2*HH*C1) * 4)
__global__ __launch_bounds__(256) void k1_conv1(const float* __restrict__ x,
                                                const float* __restrict__ w1,
                                                const float* __restrict__ b1) {
    extern __shared__ float sm[];
    float* xsm = sm;                      // [48][128]  (r = ci*3+kt, nl)
    float* w1s = xsm + 48 * 128;          // [48][128]  (r, co)
    float* b1s = w1s + 48 * 128;          // [128]
    float* xt  = b1s + 128;               // [128][67]
    float* v1s = xt + 128 * 67;           // [512]
    float* v2s = v1s + HH * C1;           // [512]

    int bt = blockIdx.x;
    int b = bt / T1, t = bt % T1;
    int n0 = blockIdx.y * 128;
    int tid = threadIdx.x;

    for (int idx = tid; idx < C0 * KTT * 128; idx += 256) {
        int r = idx >> 7, nl = idx & 127;
        int ci = r / KTT, kt = r % KTT;
        xsm[idx] = x[((b * C0 + ci) * TT + (t + kt)) * NN + n0 + nl];
    }
    for (int idx = tid; idx < 48 * 128; idx += 256) {
        int r = idx >> 7, co = idx & 127;
        int ci = r / KTT, kt = r % KTT;
        w1s[idx] = w1[(co * C0 + ci) * KTT + kt];
    }
    if (tid < 128) b1s[tid] = b1[tid];
    for (int idx = tid; idx < HH * C1; idx += 256) {
        v1s[idx] = g_v1[idx];
        v2s[idx] = g_v2[idx];
    }
    __syncthreads();

    int cidx = tid & 15;            // co group: co = cidx*4..+3 (+64 gate)
    int ng   = tid >> 4;            // 0..15
    const float4* w4 = (const float4*)w1s;
    const float4* x4 = (const float4*)xsm;

    float4 bf = *((const float4*)b1s + cidx);
    float4 bg = *((const float4*)b1s + cidx + 16);

#pragma unroll
    for (int pass = 0; pass < 2; pass++) {
        int nl0 = ng * 4 + pass * 64;
        float4 f0 = bf, f1 = bf, f2 = bf, f3 = bf;
        float4 q0 = bg, q1 = bg, q2 = bg, q3 = bg;
#pragma unroll
        for (int r = 0; r < 48; r++) {
            float4 xv = x4[r * 32 + (nl0 >> 2)];
            float4 wf = w4[r * 32 + cidx];
            float4 wg = w4[r * 32 + cidx + 16];
            f0.x = fmaf(xv.x, wf.x, f0.x); f0.y = fmaf(xv.x, wf.y, f0.y);
            f0.z = fmaf(xv.x, wf.z, f0.z); f0.w = fmaf(xv.x, wf.w, f0.w);
            f1.x = fmaf(xv.y, wf.x, f1.x); f1.y = fmaf(xv.y, wf.y, f1.y);
            f1.z = fmaf(xv.y, wf.z, f1.z); f1.w = fmaf(xv.y, wf.w, f1.w);
            f2.x = fmaf(xv.z, wf.x, f2.x); f2.y = fmaf(xv.z, wf.y, f2.y);
            f2.z = fmaf(xv.z, wf.z, f2.z); f2.w = fmaf(xv.z, wf.w, f2.w);
            f3.x = fmaf(xv.w, wf.x, f3.x); f3.y = fmaf(xv.w, wf.y, f3.y);
            f3.z = fmaf(xv.w, wf.z, f3.z); f3.w = fmaf(xv.w, wf.w, f3.w);
            q0.x = fmaf(xv.x, wg.x, q0.x); q0.y = fmaf(xv.x, wg.y, q0.y);
            q0.z = fmaf(xv.x, wg.z, q0.z); q0.w = fmaf(xv.x, wg.w, q0.w);
            q1.x = fmaf(xv.y, wg.x, q1.x); q1.y = fmaf(xv.y, wg.y, q1.y);
            q1.z = fmaf(xv.y, wg.z, q1.z); q1.w = fmaf(xv.y, wg.w, q1.w);
            q2.x = fmaf(xv.z, wg.x, q2.x); q2.y = fmaf(xv.z, wg.y, q2.y);
            q2.z = fmaf(xv.z, wg.z, q2.z); q2.w = fmaf(xv.z, wg.w, q2.w);
            q3.x = fmaf(xv.w, wg.x, q3.x); q3.y = fmaf(xv.w, wg.y, q3.y);
            q3.z = fmaf(xv.w, wg.z, q3.z); q3.w = fmaf(xv.w, wg.w, q3.w);
        }
        float4 fa[4] = {f0, f1, f2, f3};
        float4 qa[4] = {q0, q1, q2, q3};
#pragma unroll
        for (int rn = 0; rn < 4; rn++) {
            int nl = nl0 + rn;
            float xin[4] = {0.f, 0.f, 0.f, 0.f};
            if (cidx < 4) {
#pragma unroll
                for (int cc = 0; cc < 4; cc++) {
                    int co = cidx * 4 + cc;     // < 16 = C0
                    xin[cc] = xsm[(co * KTT + 2) * 128 + nl];
                }
            }
            float4 f = fa[rn], q = qa[rn];
            float4 v;
            v.x = (f.x + xin[0]) / (1.f + __expf(-q.x));
            v.y = (f.y + xin[1]) / (1.f + __expf(-q.y));
            v.z = (f.z + xin[2]) / (1.f + __expf(-q.z));
            v.w = (f.w + xin[3]) / (1.f + __expf(-q.w));
            float* xr = &xt[nl * 67 + cidx * 4];
            xr[0] = v.x; xr[1] = v.y; xr[2] = v.z; xr[3] = v.w;
            *(float4*)&g_xg[(bt * NN + n0 + nl) * C1 + cidx * 4] = v;
        }
    }
    __syncthreads();

    // e-score: node nl = tid&127, head group (tid>>7)*4, float4 stores
    {
        int nl = tid & 127;
        int hb = (tid >> 7) * 4;
        const float* row = &xt[nl * 67];
        float s1[4], s2[4];
#pragma unroll
        for (int hh = 0; hh < 4; hh++) { s1[hh] = 0.f; s2[hh] = 0.f; }
#pragma unroll 4
        for (int c = 0; c < C1; c++) {
            float v = row[c];
#pragma unroll
            for (int hh = 0; hh < 4; hh++) {
                s1[hh] = fmaf(v, v1s[(hb + hh) * C1 + c], s1[hh]);
                s2[hh] = fmaf(v, v2s[(hb + hh) * C1 + c], s2[hh]);
            }
        }
        *(float4*)&g_e1[(bt * NN + n0 + nl) * HH + hb] =
            make_float4(s1[0], s1[1], s1[2], s1[3]);
#pragma unroll
        for (int hh = 0; hh < 4; hh++)
            g_e2[(bt * HH + hb + hh) * NN + n0 + nl] = s2[hh];
    }
}

// ---------------- K2: sparse GAT, heads fused; interleaved reductions -----
// grid (B*T1, 4), 256 threads (8 warps), 8 rows/warp
#define K2_SMEM ((NN*66 + HH*NN + 8*96*12) * 4)
__global__ __launch_bounds__(256, 2) void k2_gat() {
    extern __shared__ float sm[];
    float* xt  = sm;                   // [256][66]
    float* e2s = xt + NN * 66;         // [8][256]
    float* pb  = e2s + HH * NN;        // 8 x [96][12]

    int bt = blockIdx.x;
    int tid = threadIdx.x, lane = tid & 31, w = tid >> 5;

    for (int idx = tid; idx < NN * C1; idx += 256) {
        xt[(idx >> 6) * 66 + (idx & 63)] = g_xg[bt * NN * C1 + idx];
    }
    for (int idx = tid; idx < HH * NN; idx += 256) {
        e2s[idx] = g_e2[bt * HH * NN + idx];
    }
    __syncthreads();

    float* pbw = pb + w * (96 * 12);
    int cb = 2 * lane;

    for (int rr = 0; rr < 8; rr++) {
        int i = blockIdx.y * 64 + (w << 3) + rr;
        int cnt = g_cnt[i];
        if (cnt > 96) cnt = 96;
        int nch = (cnt + 31) >> 5;
        const int* nb = g_nbr + i * NN;

        const float* e1p = g_e1 + (bt * NN + i) * HH;
        float4 eA = *(const float4*)e1p;
        float4 eB = *(const float4*)(e1p + 4);
        float e1r[HH] = {eA.x, eA.y, eA.z, eA.w, eB.x, eB.y, eB.z, eB.w};

        int jreg[3];
#pragma unroll
        for (int q = 0; q < 3; q++)
            jreg[q] = (q < nch) ? nb[(q << 5) + lane] : 0;
#pragma unroll
        for (int q = 0; q < 3; q++)
            if (q < nch) pbw[((q << 5) + lane) * 12 + 8] = __int_as_float(jreg[q]);

        // ---- scores for ALL heads into registers ----
        float sc[3][HH];
        float m[HH];
#pragma unroll
        for (int h = 0; h < HH; h++) m[h] = -3.4e38f;
#pragma unroll
        for (int q = 0; q < 3; q++) {
            if (q < nch) {
                int k = (q << 5) + lane;
                int jq = jreg[q];
                bool valid = (k < cnt);
#pragma unroll
                for (int h = 0; h < HH; h++) {
                    float s = e1r[h] + e2s[h * NN + jq];
                    s = s > 0.f ? s : ALPHA * s;
                    s = valid ? s : -3.4e38f;
                    sc[q][h] = s;
                    m[h] = fmaxf(m[h], s);
                }
            }
        }
        // ---- 8 interleaved max reductions (pipelined shfl chains) ----
#pragma unroll
        for (int o = 16; o; o >>= 1) {
#pragma unroll
            for (int h = 0; h < HH; h++)
                m[h] = fmaxf(m[h], __shfl_xor_sync(0xffffffffu, m[h], o));
        }
        // ---- exp + store + partial sums ----
        float ss[HH];
#pragma unroll
        for (int h = 0; h < HH; h++) ss[h] = 0.f;
#pragma unroll
        for (int q = 0; q < 3; q++) {
            if (q < nch) {
                float* prow = &pbw[((q << 5) + lane) * 12];
#pragma unroll
                for (int h = 0; h < HH; h++) {
                    float e = __expf(sc[q][h] - m[h]);  // masked -> 0 exactly
                    ss[h] += e;
                    prow[h] = e;
                }
            }
        }
        // ---- 8 interleaved sum reductions ----
#pragma unroll
        for (int o = 16; o; o >>= 1) {
#pragma unroll
            for (int h = 0; h < HH; h++)
                ss[h] += __shfl_xor_sync(0xffffffffu, ss[h], o);
        }
        float inv[HH];
#pragma unroll
        for (int h = 0; h < HH; h++) inv[h] = 1.f / ss[h];
        __syncwarp();

        float a0[HH], a1[HH];
#pragma unroll
        for (int h = 0; h < HH; h++) { a0[h] = 0.f; a1[h] = 0.f; }

        int pcnt = nch << 5;
#pragma unroll 4
        for (int k = 0; k < pcnt; k++) {
            const float* row = pbw + k * 12;
            float4 pA = *(const float4*)(row);
            float4 pB = *(const float4*)(row + 4);
            int j = __float_as_int(row[8]);
            float2 xv = *(const float2*)(xt + j * 66 + cb);
            a0[0] = fmaf(pA.x, xv.x, a0[0]); a1[0] = fmaf(pA.x, xv.y, a1[0]);
            a0[1] = fmaf(pA.y, xv.x, a0[1]); a1[1] = fmaf(pA.y, xv.y, a1[1]);
            a0[2] = fmaf(pA.z, xv.x, a0[2]); a1[2] = fmaf(pA.z, xv.y, a1[2]);
            a0[3] = fmaf(pA.w, xv.x, a0[3]); a1[3] = fmaf(pA.w, xv.y, a1[3]);
            a0[4] = fmaf(pB.x, xv.x, a0[4]); a1[4] = fmaf(pB.x, xv.y, a1[4]);
            a0[5] = fmaf(pB.y, xv.x, a0[5]); a1[5] = fmaf(pB.y, xv.y, a1[5]);
            a0[6] = fmaf(pB.z, xv.x, a0[6]); a1[6] = fmaf(pB.z, xv.y, a1[6]);
            a0[7] = fmaf(pB.w, xv.x, a0[7]); a1[7] = fmaf(pB.w, xv.y, a1[7]);
        }
        __syncwarp();

        float g0 = 0.f, g1 = 0.f;
#pragma unroll
        for (int h = 0; h < HH; h++) {
            g0 += ftanh(a0[h] * inv[h]);
            g1 += ftanh(a1[h] * inv[h]);
        }
        float2 base = *(const float2*)(xt + i * 66 + cb);
        float2 outv;
        outv.x = base.x + g0 * 0.125f;
        outv.y = base.y + g1 * 0.125f;
        *(float2*)(g_xs + (bt * NN + i) * C1 + cb) = outv;
    }
}

// ---------------- K3a: conv2 register-tiled 4x4 + LN partials -------------
// grid (B*T2, 4): 64 nodes/block; 256 threads; thread tile = 4 nl x 4 co
#define K3A_SMEM ((192*64 + 64 + 3*64*64 + 16) * 4)
__global__ __launch_bounds__(256, 2) void k3a_conv2(const float* __restrict__ w2,
                                                    const float* __restrict__ b2) {
    extern __shared__ float sm[];
    float* w2s = sm;                    // [192][64] (ci*3+kt, co)
    float* b2s = w2s + 192 * 64;        // [64]
    float* xs3 = b2s + 64;              // [3][64][64] (kt, nl, ci)
    float* red = xs3 + 3 * 64 * 64;     // [16]

    int bt = blockIdx.x;
    int b = bt / T2, t = bt % T2;
    int n0 = blockIdx.y * 64;
    int tid = threadIdx.x, lane = tid & 31, w = tid >> 5;

    for (int idx = tid; idx < 192 * 64; idx += 256) {
        int r = idx >> 6, co = idx & 63;
        int ci = r / KTT, kt = r % KTT;
        w2s[idx] = w2[(co * C1 + ci) * KTT + kt];
    }
    if (tid < 64) b2s[tid] = b2[tid];
    for (int idx = tid; idx < 3 * 64 * 64; idx += 256) {
        int kt = idx / 4096, rem = idx & 4095;
        int nl = rem >> 6, ci = rem & 63;
        xs3[idx] = g_xs[((b * T1 + t + kt) * NN + n0 + nl) * C1 + ci];
    }
    __syncthreads();

    int cidx = tid & 15;            // co4 index (co = cidx*4 .. +3)
    int nl_b = (tid >> 4) << 2;     // node base (4 nodes)
    const float4* w4 = (const float4*)w2s;

    float4 bias = *((const float4*)b2s + cidx);
    float4 acc0 = bias, acc1 = bias, acc2 = bias, acc3 = bias;

#pragma unroll
    for (int kt = 0; kt < KTT; kt++) {
        const float* xb = xs3 + kt * 4096 + nl_b * 64;
#pragma unroll 8
        for (int ci = 0; ci < C1; ci++) {
            float4 wv = w4[(ci * KTT + kt) * 16 + cidx];
            float x0 = xb[ci];
            float x1 = xb[64 + ci];
            float x2 = xb[128 + ci];
            float x3 = xb[192 + ci];
            acc0.x = fmaf(x0, wv.x, acc0.x); acc0.y = fmaf(x0, wv.y, acc0.y);
            acc0.z = fmaf(x0, wv.z, acc0.z); acc0.w = fmaf(x0, wv.w, acc0.w);
            acc1.x = fmaf(x1, wv.x, acc1.x); acc1.y = fmaf(x1, wv.y, acc1.y);
            acc1.z = fmaf(x1, wv.z, acc1.z); acc1.w = fmaf(x1, wv.w, acc1.w);
            acc2.x = fmaf(x2, wv.x, acc2.x); acc2.y = fmaf(x2, wv.y, acc2.y);
            acc2.z = fmaf(x2, wv.z, acc2.z); acc2.w = fmaf(x2, wv.w, acc2.w);
            acc3.x = fmaf(x3, wv.x, acc3.x); acc3.y = fmaf(x3, wv.y, acc3.y);
            acc3.z = fmaf(x3, wv.z, acc3.z); acc3.w = fmaf(x3, wv.w, acc3.w);
        }
    }

    float lsum = 0.f, lsq = 0.f;
    float4 accs[4] = {acc0, acc1, acc2, acc3};
#pragma unroll
    for (int r = 0; r < 4; r++) {
        float4 res = *(const float4*)(xs3 + (2 * 64 + nl_b + r) * 64 + cidx * 4);
        float4 v;
        v.x = fmaxf(accs[r].x + res.x, 0.f);
        v.y = fmaxf(accs[r].y + res.y, 0.f);
        v.z = fmaxf(accs[r].z + res.z, 0.f);
        v.w = fmaxf(accs[r].w + res.w, 0.f);
        *(float4*)&g_ys[(bt * NN + n0 + nl_b + r) * C2 + cidx * 4] = v;
        lsum += v.x + v.y + v.z + v.w;
        lsq  += v.x * v.x + v.y * v.y + v.z * v.z + v.w * v.w;
    }

#pragma unroll
    for (int o = 16; o; o >>= 1) {
        lsum += __shfl_xor_sync(0xffffffffu, lsum, o);
        lsq  += __shfl_xor_sync(0xffffffffu, lsq,  o);
    }
    if (lane == 0) { red[w] = lsum; red[8 + w] = lsq; }
    __syncthreads();
    if (tid == 0) {
        float S = 0.f, Q = 0.f;
#pragma unroll
        for (int k = 0; k < 8; k++) { S += red[k]; Q += red[8 + k]; }
        g_part[(bt * 4 + blockIdx.y) * 2 + 0] = S;
        g_part[(bt * 4 + blockIdx.y) * 2 + 1] = Q;
    }
}

// ---------------- K3b: LN finalize + transpose write ----------------------
// grid (B*T2, 2): each block 128 nodes
#define K3B_SMEM ((128*65) * 4)
__global__ __launch_bounds__(256) void k3b_ln(float* __restrict__ out) {
    extern __shared__ float sm[];
    float* smy = sm;                    // [128][65]
    int bt = blockIdx.x;
    int b = bt / T2, t = bt % T2;
    int nbase = blockIdx.y * 128;
    int tid = threadIdx.x;

    float S = 0.f, Q = 0.f;
#pragma unroll
    for (int k = 0; k < 4; k++) {
        S += g_part[(bt * 4 + k) * 2 + 0];
        Q += g_part[(bt * 4 + k) * 2 + 1];
    }
    const float invM = 1.f / 16384.f;
    float mu = S * invM;
    float var = Q * invM - mu * mu;
    float rstd = rsqrtf(var + 1e-5f);

    for (int idx = tid; idx < 128 * C2; idx += 256) {
        int nl = idx >> 6, c = idx & 63;
        smy[nl * 65 + c] = g_ys[(bt * NN + nbase + nl) * C2 + c];
    }
    __syncthreads();

    int nl = tid & 127, n = nbase + nl;
    int coff = (tid >> 7) * 32;
    for (int cc = 0; cc < 32; cc++) {
        int c = coff + cc;
        float v = (smy[nl * 65 + c] - mu) * rstd;
        v = fmaf(v, g_lnw[c * NN + n], g_lnb[c * NN + n]);
        out[((b * C2 + c) * T2 + t) * NN + n] = v;
    }
}

// ---------------- launch ---------------------------------------------------
extern "C" void kernel_launch(void* const* d_in, const int* in_sizes, int n_in,
                              void* d_out, int out_size) {
    const float* x       = (const float*)d_in[0];
    const float* adj     = (const float*)d_in[1];
    const float* conv1_w = (const float*)d_in[2];
    const float* conv1_b = (const float*)d_in[3];
    const float* conv2_w = (const float*)d_in[4];
    const float* conv2_b = (const float*)d_in[5];
    const float* W_heads = (const float*)d_in[6];
    const float* a_heads = (const float*)d_in[7];
    const float* ln_w    = (const float*)d_in[8];
    const float* ln_b    = (const float*)d_in[9];
    float* out = (float*)d_out;

    cudaFuncSetAttribute(k1_conv1,  cudaFuncAttributeMaxDynamicSharedMemorySize, K1_SMEM);
    cudaFuncSetAttribute(k2_gat,    cudaFuncAttributeMaxDynamicSharedMemorySize, K2_SMEM);
    cudaFuncSetAttribute(k3a_conv2, cudaFuncAttributeMaxDynamicSharedMemorySize, K3A_SMEM);
    cudaFuncSetAttribute(k3b_ln,    cudaFuncAttributeMaxDynamicSharedMemorySize, K3B_SMEM);

    k0_prep<<<16, 256>>>(adj, W_heads, a_heads, ln_w, ln_b);
    k1_conv1<<<dim3(BB * T1, 2), 256, K1_SMEM>>>(x, conv1_w, conv1_b);
    k2_gat<<<dim3(BB * T1, 4), 256, K2_SMEM>>>();
    k3a_conv2<<<dim3(BB * T2, 4), 256, K3A_SMEM>>>(conv2_w, conv2_b);
    k3b_ln<<<dim3(BB * T2, 2), 256, K3B_SMEM>>>(out);
}

// round 15
// speedup vs baseline: 2.0480x; 2.0480x over previous
#include <cuda_runtime.h>
#include <math.h>

#define BB 8
#define C0 16
#define C1 64
#define C2 64
#define TT 12
#define NN 256
#define KTT 3
#define HH 8
#define T1 10
#define T2 8
#define ALPHA 0.2f

// ---------------- device scratch (no allocations allowed) ----------------
__device__ float g_v1[HH * C1];
__device__ float g_v2[HH * C1];
__device__ int   g_nbr[NN * NN];
__device__ int   g_cnt[NN];
__device__ float g_lnw[C2 * NN];            // transposed [c][n]
__device__ float g_lnb[C2 * NN];
__device__ float g_xg[BB * T1 * NN * C1];   // x_t1 in (b,t,n,c)
__device__ float g_e1[BB * T1 * HH * NN];
__device__ float g_e2[BB * T1 * HH * NN];
__device__ float g_xs[BB * T1 * NN * C1];   // x_t1 + gat
__device__ float g_ys[BB * T2 * NN * C2];   // relu(conv2)+res, (bt,n,c)
__device__ float g_part[BB * T2 * 4 * 2];   // per-chunk LN partials {S,Q}

__device__ __forceinline__ float ftanh(float x) {
    x = fminf(fmaxf(x, -15.f), 15.f);
    float e = __expf(2.f * x);
    return (e - 1.f) / (e + 1.f);
}

// ---------------- K0: prep, parallelized over 16 blocks -------------------
__global__ void k0_prep(const float* __restrict__ adj,
                        const float* __restrict__ W,
                        const float* __restrict__ a,
                        const float* __restrict__ lnw,
                        const float* __restrict__ lnb) {
    int tid = threadIdx.x, lane = tid & 31, w = tid >> 5;
    int blk = blockIdx.x;

    if (blk == 0) {
        for (int idx = tid; idx < HH * C1; idx += 256) {
            int h = idx / C1, c = idx % C1;
            const float* Wr = W + (h * C1 + c) * C1;
            const float* ar = a + h * 2 * C1;
            float s1 = 0.f, s2 = 0.f;
            for (int d = 0; d < C1; d++) {
                float wv = Wr[d];
                s1 = fmaf(wv, ar[d], s1);
                s2 = fmaf(wv, ar[C1 + d], s2);
            }
            g_v1[idx] = s1;
            g_v2[idx] = s2;
        }
    }
    // CSR via warp ballot compaction: 16 rows per block, 2 per warp
    for (int r2 = 0; r2 < 2; r2++) {
        int i = blk * 16 + w * 2 + r2;
        const float* row = adj + i * NN;
        int cnt = 0;
#pragma unroll
        for (int c = 0; c < 8; c++) {
            int j = c * 32 + lane;
            bool bset = row[j] > 0.f;
            unsigned mask = __ballot_sync(0xffffffffu, bset);
            if (bset) {
                int pos = cnt + __popc(mask & ((1u << lane) - 1));
                g_nbr[i * NN + pos] = j;
            }
            cnt += __popc(mask);
        }
        if (lane == 0) g_cnt[i] = cnt;
        int cc = cnt > 96 ? 96 : cnt;          // K2 supports up to 3 chunks
        int pc = ((cc + 31) >> 5) << 5;
        for (int k = cnt + lane; k < pc; k += 32) g_nbr[i * NN + k] = 0;
    }
    // layernorm params transposed to [c][n], strided across blocks
    for (int idx = blk * 256 + tid; idx < NN * C2; idx += 16 * 256) {
        int n = idx / C2, c = idx % C2;
        g_lnw[c * NN + n] = lnw[idx];
        g_lnb[c * NN + n] = lnb[idx];
    }
}

// ---------------- K1: conv1 + GLU gate + e-score projections -------------
// grid (B*T1, 2): each block 128 nodes; 256 threads  (round-4 measured)
#define K1_SMEM ((48*128 + 48*128 + 128 + 128*67 + 2*HH*C1) * 4)
__global__ __launch_bounds__(256) void k1_conv1(const float* __restrict__ x,
                                                const float* __restrict__ w1,
                                                const float* __restrict__ b1) {
    extern __shared__ float sm[];
    float* xsm = sm;                      // [48][128]  (ci*3+kt, nl)
    float* w1s = xsm + 48 * 128;          // [48][128]  (ci*3+kt, co)
    float* b1s = w1s + 48 * 128;          // [128]
    float* xt  = b1s + 128;               // [128][67]
    float* v1s = xt + 128 * 67;           // [512]
    float* v2s = v1s + HH * C1;           // [512]

    int bt = blockIdx.x;
    int b = bt / T1, t = bt % T1;
    int n0 = blockIdx.y * 128;
    int tid = threadIdx.x;

    for (int idx = tid; idx < C0 * KTT * 128; idx += 256) {
        int r = idx >> 7, nl = idx & 127;
        int ci = r / KTT, kt = r % KTT;
        xsm[idx] = x[((b * C0 + ci) * TT + (t + kt)) * NN + n0 + nl];
    }
    for (int idx = tid; idx < 48 * 128; idx += 256) {
        int r = idx >> 7, co = idx & 127;
        int ci = r / KTT, kt = r % KTT;
        w1s[idx] = w1[(co * C0 + ci) * KTT + kt];
    }
    if (tid < 128) b1s[tid] = b1[tid];
    for (int idx = tid; idx < HH * C1; idx += 256) {
        v1s[idx] = g_v1[idx];
        v2s[idx] = g_v2[idx];
    }
    __syncthreads();

    int co = tid & 63, g = tid >> 6;
    for (int nl = g; nl < 64; nl += 4) {
        int nl2 = nl + 64;
        float a0 = b1s[co], a1 = b1s[co + 64];
        float c0 = a0, c1 = a1;
#pragma unroll
        for (int r = 0; r < 48; r++) {
            float xva = xsm[r * 128 + nl];
            float xvb = xsm[r * 128 + nl2];
            float w0  = w1s[r * 128 + co];
            float wg  = w1s[r * 128 + co + 64];
            a0 = fmaf(xva, w0, a0);
            a1 = fmaf(xva, wg, a1);
            c0 = fmaf(xvb, w0, c0);
            c1 = fmaf(xvb, wg, c1);
        }
        float xin_a = (co < C0) ? xsm[(co * KTT + 2) * 128 + nl]  : 0.f;
        float xin_b = (co < C0) ? xsm[(co * KTT + 2) * 128 + nl2] : 0.f;
        float va = (a0 + xin_a) / (1.f + __expf(-a1));
        float vb = (c0 + xin_b) / (1.f + __expf(-c1));
        xt[nl  * 67 + co] = va;
        xt[nl2 * 67 + co] = vb;
        g_xg[(bt * NN + n0 + nl ) * C1 + co] = va;
        g_xg[(bt * NN + n0 + nl2) * C1 + co] = vb;
    }
    __syncthreads();

    // e-score: node nl = tid&127, head group (tid>>7)*4, 8 accumulators
    {
        int nl = tid & 127;
        int hb = (tid >> 7) * 4;
        const float* row = &xt[nl * 67];
        float s1[4], s2[4];
#pragma unroll
        for (int hh = 0; hh < 4; hh++) { s1[hh] = 0.f; s2[hh] = 0.f; }
#pragma unroll 4
        for (int c = 0; c < C1; c++) {
            float v = row[c];
#pragma unroll
            for (int hh = 0; hh < 4; hh++) {
                s1[hh] = fmaf(v, v1s[(hb + hh) * C1 + c], s1[hh]);
                s2[hh] = fmaf(v, v2s[(hb + hh) * C1 + c], s2[hh]);
            }
        }
#pragma unroll
        for (int hh = 0; hh < 4; hh++) {
            g_e1[(bt * HH + hb + hh) * NN + n0 + nl] = s1[hh];
            g_e2[(bt * HH + hb + hh) * NN + n0 + nl] = s2[hh];
        }
    }
}

// ---------------- K2: sparse GAT, all heads fused in matvec ---------------
// grid (B*T1, 4), 256 threads (8 warps), 8 rows/warp  (round-4 measured)
#define K2_SMEM ((NN*66 + HH*NN + 8*96*12) * 4)
__global__ __launch_bounds__(256, 2) void k2_gat() {
    extern __shared__ float sm[];
    float* xt  = sm;                   // [256][66]
    float* e2s = xt + NN * 66;         // [8][256]
    float* pb  = e2s + HH * NN;        // 8 x [96][12]

    int bt = blockIdx.x;
    int tid = threadIdx.x, lane = tid & 31, w = tid >> 5;

    for (int idx = tid; idx < NN * C1; idx += 256) {
        xt[(idx >> 6) * 66 + (idx & 63)] = g_xg[bt * NN * C1 + idx];
    }
    for (int idx = tid; idx < HH * NN; idx += 256) {
        e2s[idx] = g_e2[bt * HH * NN + idx];
    }
    __syncthreads();

    float* pbw = pb + w * (96 * 12);
    int cb = 2 * lane;

    for (int rr = 0; rr < 8; rr++) {
        int i = blockIdx.y * 64 + (w << 3) + rr;
        int cnt = g_cnt[i];
        if (cnt > 96) cnt = 96;
        int nch = (cnt + 31) >> 5;
        const int* nb = g_nbr + i * NN;

        int jreg[3];
#pragma unroll
        for (int q = 0; q < 3; q++)
            jreg[q] = (q < nch) ? nb[(q << 5) + lane] : 0;
#pragma unroll
        for (int q = 0; q < 3; q++)
            if (q < nch) pbw[((q << 5) + lane) * 12 + 8] = __int_as_float(jreg[q]);

        float inv[HH];
#pragma unroll
        for (int h = 0; h < HH; h++) {
            float e1i = g_e1[(bt * HH + h) * NN + i];
            float s[3];
            float m = -3.4e38f;
#pragma unroll
            for (int q = 0; q < 3; q++) {
                if (q < nch) {
                    int k = (q << 5) + lane;
                    float sc = e1i + e2s[h * NN + jreg[q]];
                    sc = sc > 0.f ? sc : ALPHA * sc;
                    sc = (k < cnt) ? sc : -3.4e38f;
                    s[q] = sc;
                    m = fmaxf(m, sc);
                }
            }
#pragma unroll
            for (int o = 16; o; o >>= 1)
                m = fmaxf(m, __shfl_xor_sync(0xffffffffu, m, o));
            float ss = 0.f;
#pragma unroll
            for (int q = 0; q < 3; q++) {
                if (q < nch) {
                    float e = __expf(s[q] - m);   // padded -> 0 exactly
                    ss += e;
                    pbw[((q << 5) + lane) * 12 + h] = e;
                }
            }
#pragma unroll
            for (int o = 16; o; o >>= 1)
                ss += __shfl_xor_sync(0xffffffffu, ss, o);
            inv[h] = 1.f / ss;
        }
        __syncwarp();

        float a0[HH], a1[HH];
#pragma unroll
        for (int h = 0; h < HH; h++) { a0[h] = 0.f; a1[h] = 0.f; }

        int pcnt = nch << 5;
#pragma unroll 4
        for (int k = 0; k < pcnt; k++) {
            const float* row = pbw + k * 12;
            float4 pA = *(const float4*)(row);
            float4 pB = *(const float4*)(row + 4);
            int j = __float_as_int(row[8]);
            float2 xv = *(const float2*)(xt + j * 66 + cb);
            a0[0] = fmaf(pA.x, xv.x, a0[0]); a1[0] = fmaf(pA.x, xv.y, a1[0]);
            a0[1] = fmaf(pA.y, xv.x, a0[1]); a1[1] = fmaf(pA.y, xv.y, a1[1]);
            a0[2] = fmaf(pA.z, xv.x, a0[2]); a1[2] = fmaf(pA.z, xv.y, a1[2]);
            a0[3] = fmaf(pA.w, xv.x, a0[3]); a1[3] = fmaf(pA.w, xv.y, a1[3]);
            a0[4] = fmaf(pB.x, xv.x, a0[4]); a1[4] = fmaf(pB.x, xv.y, a1[4]);
            a0[5] = fmaf(pB.y, xv.x, a0[5]); a1[5] = fmaf(pB.y, xv.y, a1[5]);
            a0[6] = fmaf(pB.z, xv.x, a0[6]); a1[6] = fmaf(pB.z, xv.y, a1[6]);
            a0[7] = fmaf(pB.w, xv.x, a0[7]); a1[7] = fmaf(pB.w, xv.y, a1[7]);
        }
        __syncwarp();

        float g0 = 0.f, g1 = 0.f;
#pragma unroll
        for (int h = 0; h < HH; h++) {
            g0 += ftanh(a0[h] * inv[h]);
            g1 += ftanh(a1[h] * inv[h]);
        }
        float2 base = *(const float2*)(xt + i * 66 + cb);
        float2 outv;
        outv.x = base.x + g0 * 0.125f;
        outv.y = base.y + g1 * 0.125f;
        *(float2*)(g_xs + (bt * NN + i) * C1 + cb) = outv;
    }
}

// ---------------- K3a: conv2 register-tiled 4x4 + LN partials -------------
// grid (B*T2, 4): 64 nodes/block; 256 threads  (round-5, measured 33.8us)
#define K3A_SMEM ((192*64 + 64 + 3*64*64 + 16) * 4)
__global__ __launch_bounds__(256, 2) void k3a_conv2(const float* __restrict__ w2,
                                                    const float* __restrict__ b2) {
    extern __shared__ float sm[];
    float* w2s = sm;                    // [192][64] (ci*3+kt, co)
    float* b2s = w2s + 192 * 64;        // [64]
    float* xs3 = b2s + 64;              // [3][64][64] (kt, nl, ci)
    float* red = xs3 + 3 * 64 * 64;     // [16]

    int bt = blockIdx.x;
    int b = bt / T2, t = bt % T2;
    int n0 = blockIdx.y * 64;
    int tid = threadIdx.x, lane = tid & 31, w = tid >> 5;

    for (int idx = tid; idx < 192 * 64; idx += 256) {
        int r = idx >> 6, co = idx & 63;
        int ci = r / KTT, kt = r % KTT;
        w2s[idx] = w2[(co * C1 + ci) * KTT + kt];
    }
    if (tid < 64) b2s[tid] = b2[tid];
    for (int idx = tid; idx < 3 * 64 * 64; idx += 256) {
        int kt = idx / 4096, rem = idx & 4095;
        int nl = rem >> 6, ci = rem & 63;
        xs3[idx] = g_xs[((b * T1 + t + kt) * NN + n0 + nl) * C1 + ci];
    }
    __syncthreads();

    int cidx = tid & 15;            // co4 index (co = cidx*4 .. +3)
    int nl_b = (tid >> 4) << 2;     // node base (4 nodes)
    const float4* w4 = (const float4*)w2s;

    float4 bias = *((const float4*)b2s + cidx);
    float4 acc0 = bias, acc1 = bias, acc2 = bias, acc3 = bias;

#pragma unroll
    for (int kt = 0; kt < KTT; kt++) {
        const float* xb = xs3 + kt * 4096 + nl_b * 64;
#pragma unroll 8
        for (int ci = 0; ci < C1; ci++) {
            float4 wv = w4[(ci * KTT + kt) * 16 + cidx];
            float x0 = xb[ci];
            float x1 = xb[64 + ci];
            float x2 = xb[128 + ci];
            float x3 = xb[192 + ci];
            acc0.x = fmaf(x0, wv.x, acc0.x); acc0.y = fmaf(x0, wv.y, acc0.y);
            acc0.z = fmaf(x0, wv.z, acc0.z); acc0.w = fmaf(x0, wv.w, acc0.w);
            acc1.x = fmaf(x1, wv.x, acc1.x); acc1.y = fmaf(x1, wv.y, acc1.y);
            acc1.z = fmaf(x1, wv.z, acc1.z); acc1.w = fmaf(x1, wv.w, acc1.w);
            acc2.x = fmaf(x2, wv.x, acc2.x); acc2.y = fmaf(x2, wv.y, acc2.y);
            acc2.z = fmaf(x2, wv.z, acc2.z); acc2.w = fmaf(x2, wv.w, acc2.w);
            acc3.x = fmaf(x3, wv.x, acc3.x); acc3.y = fmaf(x3, wv.y, acc3.y);
            acc3.z = fmaf(x3, wv.z, acc3.z); acc3.w = fmaf(x3, wv.w, acc3.w);
        }
    }

    float lsum = 0.f, lsq = 0.f;
    float4 accs[4] = {acc0, acc1, acc2, acc3};
#pragma unroll
    for (int r = 0; r < 4; r++) {
        float4 res = *(const float4*)(xs3 + (2 * 64 + nl_b + r) * 64 + cidx * 4);
        float4 v;
        v.x = fmaxf(accs[r].x + res.x, 0.f);
        v.y = fmaxf(accs[r].y + res.y, 0.f);
        v.z = fmaxf(accs[r].z + res.z, 0.f);
        v.w = fmaxf(accs[r].w + res.w, 0.f);
        *(float4*)&g_ys[(bt * NN + n0 + nl_b + r) * C2 + cidx * 4] = v;
        lsum += v.x + v.y + v.z + v.w;
        lsq  += v.x * v.x + v.y * v.y + v.z * v.z + v.w * v.w;
    }

#pragma unroll
    for (int o = 16; o; o >>= 1) {
        lsum += __shfl_xor_sync(0xffffffffu, lsum, o);
        lsq  += __shfl_xor_sync(0xffffffffu, lsq,  o);
    }
    if (lane == 0) { red[w] = lsum; red[8 + w] = lsq; }
    __syncthreads();
    if (tid == 0) {
        float S = 0.f, Q = 0.f;
#pragma unroll
        for (int k = 0; k < 8; k++) { S += red[k]; Q += red[8 + k]; }
        g_part[(bt * 4 + blockIdx.y) * 2 + 0] = S;
        g_part[(bt * 4 + blockIdx.y) * 2 + 1] = Q;
    }
}

// ---------------- K3b: LN finalize + transpose write ----------------------
// grid (B*T2, 2): each block 128 nodes  (round-4 measured)
#define K3B_SMEM ((128*65) * 4)
__global__ __launch_bounds__(256) void k3b_ln(float* __restrict__ out) {
    extern __shared__ float sm[];
    float* smy = sm;                    // [128][65]
    int bt = blockIdx.x;
    int b = bt / T2, t = bt % T2;
    int nbase = blockIdx.y * 128;
    int tid = threadIdx.x;

    float S = 0.f, Q = 0.f;
#pragma unroll
    for (int k = 0; k < 4; k++) {
        S += g_part[(bt * 4 + k) * 2 + 0];
        Q += g_part[(bt * 4 + k) * 2 + 1];
    }
    const float invM = 1.f / 16384.f;
    float mu = S * invM;
    float var = Q * invM - mu * mu;
    float rstd = rsqrtf(var + 1e-5f);

    for (int idx = tid; idx < 128 * C2; idx += 256) {
        int nl = idx >> 6, c = idx & 63;
        smy[nl * 65 + c] = g_ys[(bt * NN + nbase + nl) * C2 + c];
    }
    __syncthreads();

    int nl = tid & 127, n = nbase + nl;
    int coff = (tid >> 7) * 32;
    for (int cc = 0; cc < 32; cc++) {
        int c = coff + cc;
        float v = (smy[nl * 65 + c] - mu) * rstd;
        v = fmaf(v, g_lnw[c * NN + n], g_lnb[c * NN + n]);
        out[((b * C2 + c) * T2 + t) * NN + n] = v;
    }
}

// ---------------- launch ---------------------------------------------------
extern "C" void kernel_launch(void* const* d_in, const int* in_sizes, int n_in,
                              void* d_out, int out_size) {
    const float* x       = (const float*)d_in[0];
    const float* adj     = (const float*)d_in[1];
    const float* conv1_w = (const float*)d_in[2];
    const float* conv1_b = (const float*)d_in[3];
    const float* conv2_w = (const float*)d_in[4];
    const float* conv2_b = (const float*)d_in[5];
    const float* W_heads = (const float*)d_in[6];
    const float* a_heads = (const float*)d_in[7];
    const float* ln_w    = (const float*)d_in[8];
    const float* ln_b    = (const float*)d_in[9];
    float* out = (float*)d_out;

    cudaFuncSetAttribute(k1_conv1,  cudaFuncAttributeMaxDynamicSharedMemorySize, K1_SMEM);
    cudaFuncSetAttribute(k2_gat,    cudaFuncAttributeMaxDynamicSharedMemorySize, K2_SMEM);
    cudaFuncSetAttribute(k3a_conv2, cudaFuncAttributeMaxDynamicSharedMemorySize, K3A_SMEM);
    cudaFuncSetAttribute(k3b_ln,    cudaFuncAttributeMaxDynamicSharedMemorySize, K3B_SMEM);

    k0_prep<<<16, 256>>>(adj, W_heads, a_heads, ln_w, ln_b);
    k1_conv1<<<dim3(BB * T1, 2), 256, K1_SMEM>>>(x, conv1_w, conv1_b);
    k2_gat<<<dim3(BB * T1, 4), 256, K2_SMEM>>>();
    k3a_conv2<<<dim3(BB * T2, 4), 256, K3A_SMEM>>>(conv2_w, conv2_b);
    k3b_ln<<<dim3(BB * T2, 2), 256, K3B_SMEM>>>(out);
}